// round 1
// baseline (speedup 1.0000x reference)
#include <cuda_runtime.h>
#include <cuda_bf16.h>

#define NNODES 100000
#define NEDGES 1600000
#define HID 64
#define FIN 128
#define NOUT 32

// ---------------- scratch (static device globals; no allocation) -------------
__device__ float    g_h[NNODES * HID];     // h = x @ W (gather source)
__device__ float    g_agg[NNODES * HID];   // aggregation target (init to bias)
__device__ float    g_as[NNODES];
__device__ float    g_ad[NNODES];
__device__ float    g_ssum[NNODES];
__device__ unsigned g_mkey[NNODES];
__device__ float    g_e[NEDGES];           // e, then overwritten with exp(e-m)

// ---------------- helpers ----------------------------------------------------
__device__ __forceinline__ unsigned enc_f(float f) {
    unsigned u = __float_as_uint(f);
    return (u & 0x80000000u) ? ~u : (u | 0x80000000u);
}
__device__ __forceinline__ float dec_f(unsigned k) {
    return (k & 0x80000000u) ? __uint_as_float(k & 0x7FFFFFFFu)
                             : __uint_as_float(~k);
}

// ---------------- GEMM: C[n,64] = X[n,K] @ W[K,64] ---------------------------
template <int K>
__global__ void gemm_kernel(const float* __restrict__ X,
                            const float* __restrict__ W,
                            float* __restrict__ C, int n) {
    __shared__ float Ws[K * 64];
    __shared__ float Xs[16 * K];
    int tid = threadIdx.x;
    for (int i = tid; i < K * 64; i += 256) Ws[i] = W[i];
    int nbase = blockIdx.x * 16;
    for (int i = tid; i < 16 * K; i += 256) {
        int r = i / K, c = i % K;
        int nd = nbase + r;
        Xs[r * K + c] = (nd < n) ? X[nd * K + c] : 0.f;
    }
    __syncthreads();
    int r = tid >> 4;          // node within tile (0..15)
    int c0 = tid & 15;         // cols c0, c0+16, c0+32, c0+48
    float a0 = 0.f, a1 = 0.f, a2 = 0.f, a3 = 0.f;
#pragma unroll
    for (int k = 0; k < K; k++) {
        float xv = Xs[r * K + k];
        a0 += xv * Ws[k * 64 + c0];
        a1 += xv * Ws[k * 64 + c0 + 16];
        a2 += xv * Ws[k * 64 + c0 + 32];
        a3 += xv * Ws[k * 64 + c0 + 48];
    }
    int nd = nbase + r;
    if (nd < n) {
        C[nd * 64 + c0]      = a0;
        C[nd * 64 + c0 + 16] = a1;
        C[nd * 64 + c0 + 32] = a2;
        C[nd * 64 + c0 + 48] = a3;
    }
}

// ---------------- per-node attention scores: warp per node -------------------
__global__ void score_kernel(const float* __restrict__ h,
                             const float* __restrict__ att_s,
                             const float* __restrict__ att_d,
                             float* __restrict__ as_, float* __restrict__ ad_,
                             int n) {
    int gt = blockIdx.x * blockDim.x + threadIdx.x;
    int nd = gt >> 5;
    int lane = gt & 31;
    if (nd >= n) return;
    float h0 = h[nd * 64 + lane];
    float h1 = h[nd * 64 + 32 + lane];
    float vs = h0 * att_s[lane] + h1 * att_s[32 + lane];
    float vd = h0 * att_d[lane] + h1 * att_d[32 + lane];
#pragma unroll
    for (int o = 16; o; o >>= 1) {
        vs += __shfl_xor_sync(0xFFFFFFFFu, vs, o);
        vd += __shfl_xor_sync(0xFFFFFFFFu, vd, o);
    }
    if (lane == 0) { as_[nd] = vs; ad_[nd] = vd; }
}

// ---------------- init agg=bias, ssum=0, mkey=0 ------------------------------
__global__ void init_kernel(float* __restrict__ agg, const float* __restrict__ b,
                            float* __restrict__ ssum, unsigned* __restrict__ mkey,
                            int n) {
    int i = blockIdx.x * blockDim.x + threadIdx.x;
    if (i >= n * 64) return;
    agg[i] = b[i & 63];
    if ((i & 63) == 0) {
        int nd = i >> 6;
        ssum[nd] = 0.f;
        mkey[nd] = 0u;
    }
}

// ---------------- edge pass 1: e + segment max -------------------------------
__global__ void edge_max_kernel(const int* __restrict__ src,
                                const int* __restrict__ dst,
                                const float* __restrict__ as_,
                                const float* __restrict__ ad_,
                                float* __restrict__ e,
                                unsigned* __restrict__ mkey, int ne) {
    int i = blockIdx.x * blockDim.x + threadIdx.x;
    if (i >= ne) return;
    int s = src[i], d = dst[i];
    float v = as_[s] + ad_[d];
    v = (v > 0.f) ? v : 0.2f * v;
    e[i] = v;
    atomicMax(&mkey[d], enc_f(v));
}

// ---------------- edge pass 2: exp + segment sum -----------------------------
__global__ void edge_exp_kernel(const int* __restrict__ dst,
                                float* __restrict__ e,
                                const unsigned* __restrict__ mkey,
                                float* __restrict__ ssum, int ne) {
    int i = blockIdx.x * blockDim.x + threadIdx.x;
    if (i >= ne) return;
    int d = dst[i];
    float m = dec_f(mkey[d]);
    float ex = expf(e[i] - m);
    e[i] = ex;
    atomicAdd(&ssum[d], ex);
}

// ---------------- edge pass 3: weighted aggregation --------------------------
// 16 lanes per edge, each lane owns 4 features (float4 gather + vector RED).
__global__ void edge_aggr_kernel(const int* __restrict__ src,
                                 const int* __restrict__ dst,
                                 const float* __restrict__ ex,
                                 const float* __restrict__ ssum,
                                 const float* __restrict__ h,
                                 float* __restrict__ agg, int ne) {
    int gt = blockIdx.x * blockDim.x + threadIdx.x;
    int g = gt >> 4;
    int lane = gt & 15;
    if (g >= ne) return;
    int s = src[g], d = dst[g];
    float alpha = ex[g] / (ssum[d] + 1e-16f);
    const float4 hv = *reinterpret_cast<const float4*>(h + (size_t)s * 64 + lane * 4);
    float vx = hv.x * alpha, vy = hv.y * alpha, vz = hv.z * alpha, vw = hv.w * alpha;
    float* p = agg + (size_t)d * 64 + lane * 4;
    asm volatile("red.global.add.v4.f32 [%0], {%1, %2, %3, %4};"
                 :: "l"(p), "f"(vx), "f"(vy), "f"(vz), "f"(vw) : "memory");
}

// ---------------- in-place ReLU ----------------------------------------------
__global__ void relu_kernel(float* __restrict__ a, int total) {
    int i = blockIdx.x * blockDim.x + threadIdx.x;
    if (i >= total) return;
    float v = a[i];
    a[i] = v > 0.f ? v : 0.f;
}

// ---------------- final: out = log_softmax(agg @ Wlin + blin) ----------------
// warp per node, lane = output column (32 cols).
__global__ void final_kernel(const float* __restrict__ agg,
                             const float* __restrict__ Wlin,
                             const float* __restrict__ blin,
                             float* __restrict__ out, int n) {
    __shared__ float Ws[64 * 32];
    for (int i = threadIdx.x; i < 64 * 32; i += blockDim.x) Ws[i] = Wlin[i];
    __syncthreads();
    int gt = blockIdx.x * blockDim.x + threadIdx.x;
    int nd = gt >> 5;
    int lane = gt & 31;
    if (nd >= n) return;
    const float* hr = agg + (size_t)nd * 64;
    float acc = blin[lane];
#pragma unroll
    for (int k = 0; k < 64; k++) acc += hr[k] * Ws[k * 32 + lane];
    float m = acc;
#pragma unroll
    for (int o = 16; o; o >>= 1) m = fmaxf(m, __shfl_xor_sync(0xFFFFFFFFu, m, o));
    float ex = expf(acc - m);
    float ss = ex;
#pragma unroll
    for (int o = 16; o; o >>= 1) ss += __shfl_xor_sync(0xFFFFFFFFu, ss, o);
    out[(size_t)nd * 32 + lane] = acc - m - logf(ss);
}

// ---------------- launch ------------------------------------------------------
extern "C" void kernel_launch(void* const* d_in, const int* in_sizes, int n_in,
                              void* d_out, int out_size) {
    const float* x        = (const float*)d_in[0];
    const int*   ei1      = (const int*)d_in[1];
    const int*   ei2      = (const int*)d_in[2];
    const float* W1       = (const float*)d_in[3];
    const float* att_src1 = (const float*)d_in[4];
    const float* att_dst1 = (const float*)d_in[5];
    const float* b1       = (const float*)d_in[6];
    const float* W2       = (const float*)d_in[7];
    const float* att_src2 = (const float*)d_in[8];
    const float* att_dst2 = (const float*)d_in[9];
    const float* b2       = (const float*)d_in[10];
    const float* Wlin     = (const float*)d_in[11];
    const float* blin     = (const float*)d_in[12];
    float* out = (float*)d_out;

    const int n = in_sizes[0] / FIN;       // 100000
    const int e = in_sizes[1] / 2;         // 1600000

    float *h, *agg, *as_, *ad_, *ssum, *ebuf;
    unsigned* mkey;
    cudaGetSymbolAddress((void**)&h,    g_h);
    cudaGetSymbolAddress((void**)&agg,  g_agg);
    cudaGetSymbolAddress((void**)&as_,  g_as);
    cudaGetSymbolAddress((void**)&ad_,  g_ad);
    cudaGetSymbolAddress((void**)&ssum, g_ssum);
    cudaGetSymbolAddress((void**)&mkey, g_mkey);
    cudaGetSymbolAddress((void**)&ebuf, g_e);

    const int TB = 256;
    int gemm_blocks  = (n + 15) / 16;
    int node64_blocks = (n * 64 + TB - 1) / TB;
    int warp_blocks  = (n * 32 + TB - 1) / TB;
    int edge_blocks  = (e + TB - 1) / TB;
    int aggr_blocks  = (e * 16 + TB - 1) / TB;   // 16 lanes per edge

    // ---------------- layer 1 ----------------
    gemm_kernel<FIN><<<gemm_blocks, TB>>>(x, W1, h, n);
    score_kernel<<<warp_blocks, TB>>>(h, att_src1, att_dst1, as_, ad_, n);
    init_kernel<<<node64_blocks, TB>>>(agg, b1, ssum, mkey, n);
    edge_max_kernel<<<edge_blocks, TB>>>(ei1, ei1 + e, as_, ad_, ebuf, mkey, e);
    edge_exp_kernel<<<edge_blocks, TB>>>(ei1 + e, ebuf, mkey, ssum, e);
    edge_aggr_kernel<<<aggr_blocks, TB>>>(ei1, ei1 + e, ebuf, ssum, h, agg, e);
    relu_kernel<<<node64_blocks, TB>>>(agg, n * 64);

    // ---------------- layer 2 ----------------
    gemm_kernel<HID><<<gemm_blocks, TB>>>(agg, W2, h, n);
    score_kernel<<<warp_blocks, TB>>>(h, att_src2, att_dst2, as_, ad_, n);
    init_kernel<<<node64_blocks, TB>>>(agg, b2, ssum, mkey, n);
    edge_max_kernel<<<edge_blocks, TB>>>(ei2, ei2 + e, as_, ad_, ebuf, mkey, e);
    edge_exp_kernel<<<edge_blocks, TB>>>(ei2 + e, ebuf, mkey, ssum, e);
    edge_aggr_kernel<<<aggr_blocks, TB>>>(ei2, ei2 + e, ebuf, ssum, h, agg, e);

    // ---------------- readout ----------------
    final_kernel<<<warp_blocks, TB>>>(agg, Wlin, blin, out, n);
}

// round 3
// speedup vs baseline: 1.1951x; 1.1951x over previous
#include <cuda_runtime.h>
#include <cuda_bf16.h>
#include <math_constants.h>

#define NNODES 100000
#define NEDGES 1600000
#define HID 64
#define FIN 128
#define NOUT 32
#define SCAN_CHUNK 1024
#define FULLMASK 0xFFFFFFFFu

// ---------------- scratch (static device globals; no allocation) -------------
__device__ float g_h[NNODES * HID];       // h = x @ W (gather source)
__device__ float g_agg[NNODES * HID];     // layer output
__device__ float g_as[NNODES];
__device__ float g_ad[NNODES];
__device__ int   g_deg[NNODES];
__device__ int   g_rowptr[NNODES + 1];
__device__ int   g_cur[NNODES];
__device__ int   g_csr[NEDGES];
__device__ int   g_bsum[256];

// ---------------- GEMM: C[n,64] = X[n,K] @ W[K,64], 64x64 tile, 4x4/thread ---
template <int K>
__global__ void gemm64_kernel(const float* __restrict__ X,
                              const float* __restrict__ W,
                              float* __restrict__ C, int n) {
    __shared__ float Xs[64][33];     // [row][kk], padded
    __shared__ float Ws[32][64];     // [kk][col]
    int tid = threadIdx.x;
    int tx = tid & 15;               // col group (4 cols)
    int ty = tid >> 4;               // row group (4 rows)
    int row0 = blockIdx.x * 64;
    float acc[4][4] = {};
    for (int k0 = 0; k0 < K; k0 += 32) {
        // load X chunk: 64 rows x 32 k = 512 float4
        for (int l = tid; l < 512; l += 256) {
            int r = l >> 3, c4 = l & 7;
            int nd = row0 + r;
            float4 v = make_float4(0.f, 0.f, 0.f, 0.f);
            if (nd < n) v = *reinterpret_cast<const float4*>(X + (size_t)nd * K + k0 + c4 * 4);
            Xs[r][c4 * 4 + 0] = v.x; Xs[r][c4 * 4 + 1] = v.y;
            Xs[r][c4 * 4 + 2] = v.z; Xs[r][c4 * 4 + 3] = v.w;
        }
        // load W chunk: 32 kk x 64 cols = 512 float4
        for (int l = tid; l < 512; l += 256) {
            int kk = l >> 4, c4 = l & 15;
            *reinterpret_cast<float4*>(&Ws[kk][c4 * 4]) =
                *reinterpret_cast<const float4*>(W + (size_t)(k0 + kk) * 64 + c4 * 4);
        }
        __syncthreads();
#pragma unroll
        for (int kk = 0; kk < 32; kk++) {
            float4 wv = *reinterpret_cast<float4*>(&Ws[kk][tx * 4]);
#pragma unroll
            for (int r = 0; r < 4; r++) {
                float xv = Xs[ty * 4 + r][kk];
                acc[r][0] += xv * wv.x; acc[r][1] += xv * wv.y;
                acc[r][2] += xv * wv.z; acc[r][3] += xv * wv.w;
            }
        }
        __syncthreads();
    }
#pragma unroll
    for (int r = 0; r < 4; r++) {
        int nd = row0 + ty * 4 + r;
        if (nd < n)
            *reinterpret_cast<float4*>(C + (size_t)nd * 64 + tx * 4) =
                make_float4(acc[r][0], acc[r][1], acc[r][2], acc[r][3]);
    }
}

// ---------------- per-node attention scores: warp per node -------------------
__global__ void score_kernel(const float* __restrict__ h,
                             const float* __restrict__ att_s,
                             const float* __restrict__ att_d,
                             float* __restrict__ as_, float* __restrict__ ad_,
                             int n) {
    int gt = blockIdx.x * blockDim.x + threadIdx.x;
    int nd = gt >> 5;
    int lane = gt & 31;
    if (nd >= n) return;
    float h0 = h[(size_t)nd * 64 + lane];
    float h1 = h[(size_t)nd * 64 + 32 + lane];
    float vs = h0 * att_s[lane] + h1 * att_s[32 + lane];
    float vd = h0 * att_d[lane] + h1 * att_d[32 + lane];
#pragma unroll
    for (int o = 16; o; o >>= 1) {
        vs += __shfl_xor_sync(FULLMASK, vs, o);
        vd += __shfl_xor_sync(FULLMASK, vd, o);
    }
    if (lane == 0) { as_[nd] = vs; ad_[nd] = vd; }
}

// ---------------- CSR build --------------------------------------------------
__global__ void zero_deg_kernel(int* __restrict__ deg, int n) {
    int i = blockIdx.x * blockDim.x + threadIdx.x;
    if (i < n) deg[i] = 0;
}

__global__ void hist_kernel(const int* __restrict__ dst, int* __restrict__ deg, int ne) {
    int i = blockIdx.x * blockDim.x + threadIdx.x;
    if (i < ne) atomicAdd(&deg[dst[i]], 1);
}

// block-level exclusive scan of deg (1024 elems / block of 256 threads)
__global__ void scan_block_kernel(const int* __restrict__ deg,
                                  int* __restrict__ rowptr,
                                  int* __restrict__ bsum, int n) {
    __shared__ int tsum[256];
    int t = threadIdx.x;
    int base = blockIdx.x * SCAN_CHUNK + t * 4;
    int v[4]; int s = 0;
#pragma unroll
    for (int j = 0; j < 4; j++) { v[j] = (base + j < n) ? deg[base + j] : 0; s += v[j]; }
    tsum[t] = s;
    __syncthreads();
    int acc = s;
    for (int off = 1; off < 256; off <<= 1) {
        int x = (t >= off) ? tsum[t - off] : 0;
        __syncthreads();
        tsum[t] += x;
        __syncthreads();
    }
    int excl = tsum[t] - acc;
    if (t == 255) bsum[blockIdx.x] = tsum[255];
    int run = excl;
#pragma unroll
    for (int j = 0; j < 4; j++) {
        if (base + j < n) rowptr[base + j] = run;
        run += v[j];
    }
}

// single-block exclusive scan over block sums (nb <= 256)
__global__ void scan_partials_kernel(int* __restrict__ bsum, int nb) {
    __shared__ int sm[256];
    int t = threadIdx.x;
    int v = (t < nb) ? bsum[t] : 0;
    sm[t] = v;
    __syncthreads();
    for (int off = 1; off < 256; off <<= 1) {
        int x = (t >= off) ? sm[t - off] : 0;
        __syncthreads();
        sm[t] += x;
        __syncthreads();
    }
    if (t < nb) bsum[t] = sm[t] - v;   // exclusive
}

__global__ void scan_add_kernel(int* __restrict__ rowptr, int* __restrict__ cur,
                                const int* __restrict__ bsum, int n, int e) {
    int i = blockIdx.x * blockDim.x + threadIdx.x;
    if (i < n) {
        int v = rowptr[i] + bsum[i >> 10];
        rowptr[i] = v;
        cur[i] = v;
    }
    if (i == 0) rowptr[n] = e;
}

__global__ void scatter_kernel(const int* __restrict__ src, const int* __restrict__ dst,
                               int* __restrict__ cur, int* __restrict__ csr, int ne) {
    int i = blockIdx.x * blockDim.x + threadIdx.x;
    if (i >= ne) return;
    int d = dst[i];
    int p = atomicAdd(&cur[d], 1);
    csr[p] = src[i];
}

// ---------------- fused softmax + aggregation: warp per dst node -------------
__global__ void aggr_kernel(const int* __restrict__ rowptr,
                            const int* __restrict__ csr,
                            const float* __restrict__ as_,
                            const float* __restrict__ ad_,
                            const float* __restrict__ h,
                            const float* __restrict__ bias,
                            float* __restrict__ aggout, int n, int do_relu) {
    int gt = blockIdx.x * blockDim.x + threadIdx.x;
    int nd = gt >> 5;
    int lane = gt & 31;
    if (nd >= n) return;
    int start = rowptr[nd];
    int end = rowptr[nd + 1];
    float adv = ad_[nd];

    // pass 1: online segment max + sum
    float m = -CUDART_INF_F;
    float ssum = 0.f;
    for (int base = start; base < end; base += 32) {
        int i = base + lane;
        float e = -CUDART_INF_F;
        if (i < end) {
            int s = csr[i];
            float v = as_[s] + adv;
            e = (v > 0.f) ? v : 0.2f * v;
        }
        float cm = e;
#pragma unroll
        for (int o = 16; o; o >>= 1) cm = fmaxf(cm, __shfl_xor_sync(FULLMASK, cm, o));
        float mnew = fmaxf(m, cm);               // cm finite since base<end
        float scale = __expf(m - mnew);           // m=-inf first iter -> 0
        float ex = (i < end) ? __expf(e - mnew) : 0.f;
#pragma unroll
        for (int o = 16; o; o >>= 1) ex += __shfl_xor_sync(FULLMASK, ex, o);
        ssum = ssum * scale + ex;
        m = mnew;
    }
    float inv = 1.f / (ssum + 1e-16f);

    // pass 2: weighted feature accumulation (2 features/lane in registers)
    float a0 = 0.f, a1 = 0.f;
    for (int base = start; base < end; base += 32) {
        int i = base + lane;
        int s = 0;
        float alpha = 0.f;
        if (i < end) {
            s = csr[i];
            float v = as_[s] + adv;
            v = (v > 0.f) ? v : 0.2f * v;
            alpha = __expf(v - m) * inv;
        }
        int cnt = min(32, end - base);
        for (int j = 0; j < cnt; j++) {
            int sj = __shfl_sync(FULLMASK, s, j);
            float aj = __shfl_sync(FULLMASK, alpha, j);
            float2 hv = *reinterpret_cast<const float2*>(h + (size_t)sj * 64 + lane * 2);
            a0 += aj * hv.x;
            a1 += aj * hv.y;
        }
    }
    float o0 = a0 + bias[lane * 2];
    float o1 = a1 + bias[lane * 2 + 1];
    if (do_relu) { o0 = fmaxf(o0, 0.f); o1 = fmaxf(o1, 0.f); }
    *reinterpret_cast<float2*>(aggout + (size_t)nd * 64 + lane * 2) = make_float2(o0, o1);
}

// ---------------- final: out = log_softmax(agg @ Wlin + blin) ----------------
__global__ void final_kernel(const float* __restrict__ agg,
                             const float* __restrict__ Wlin,
                             const float* __restrict__ blin,
                             float* __restrict__ out, int n) {
    __shared__ float Ws[64 * 32];
    for (int i = threadIdx.x; i < 64 * 32; i += blockDim.x) Ws[i] = Wlin[i];
    __syncthreads();
    int gt = blockIdx.x * blockDim.x + threadIdx.x;
    int nd = gt >> 5;
    int lane = gt & 31;
    if (nd >= n) return;
    const float* hr = agg + (size_t)nd * 64;
    float acc = blin[lane];
#pragma unroll
    for (int k = 0; k < 64; k++) acc += hr[k] * Ws[k * 32 + lane];
    float m = acc;
#pragma unroll
    for (int o = 16; o; o >>= 1) m = fmaxf(m, __shfl_xor_sync(FULLMASK, m, o));
    float ex = __expf(acc - m);
    float ss = ex;
#pragma unroll
    for (int o = 16; o; o >>= 1) ss += __shfl_xor_sync(FULLMASK, ss, o);
    out[(size_t)nd * 32 + lane] = acc - m - __logf(ss);
}

// ---------------- launch ------------------------------------------------------
extern "C" void kernel_launch(void* const* d_in, const int* in_sizes, int n_in,
                              void* d_out, int out_size) {
    const float* x        = (const float*)d_in[0];
    const int*   ei1      = (const int*)d_in[1];
    const int*   ei2      = (const int*)d_in[2];
    const float* W1       = (const float*)d_in[3];
    const float* att_src1 = (const float*)d_in[4];
    const float* att_dst1 = (const float*)d_in[5];
    const float* b1       = (const float*)d_in[6];
    const float* W2       = (const float*)d_in[7];
    const float* att_src2 = (const float*)d_in[8];
    const float* att_dst2 = (const float*)d_in[9];
    const float* b2       = (const float*)d_in[10];
    const float* Wlin     = (const float*)d_in[11];
    const float* blin     = (const float*)d_in[12];
    float* out = (float*)d_out;

    const int n = in_sizes[0] / FIN;       // 100000
    const int e = in_sizes[1] / 2;         // 1600000

    float *h, *agg, *as_, *ad_;
    int *deg, *rowptr, *cur, *csr, *bsum;
    cudaGetSymbolAddress((void**)&h,      g_h);
    cudaGetSymbolAddress((void**)&agg,    g_agg);
    cudaGetSymbolAddress((void**)&as_,    g_as);
    cudaGetSymbolAddress((void**)&ad_,    g_ad);
    cudaGetSymbolAddress((void**)&deg,    g_deg);
    cudaGetSymbolAddress((void**)&rowptr, g_rowptr);
    cudaGetSymbolAddress((void**)&cur,    g_cur);
    cudaGetSymbolAddress((void**)&csr,    g_csr);
    cudaGetSymbolAddress((void**)&bsum,   g_bsum);

    const int TB = 256;
    int gemm_blocks  = (n + 63) / 64;
    int node_blocks  = (n + TB - 1) / TB;
    int warp_blocks  = (n * 32 + TB - 1) / TB;
    int edge_blocks  = (e + TB - 1) / TB;
    int scan_blocks  = (n + SCAN_CHUNK - 1) / SCAN_CHUNK;   // 98

    // ================= layer 1 =================
    gemm64_kernel<FIN><<<gemm_blocks, TB>>>(x, W1, h, n);
    score_kernel<<<warp_blocks, TB>>>(h, att_src1, att_dst1, as_, ad_, n);
    // CSR by dst (independent of gemm/score)
    zero_deg_kernel<<<node_blocks, TB>>>(deg, n);
    hist_kernel<<<edge_blocks, TB>>>(ei1 + e, deg, e);
    scan_block_kernel<<<scan_blocks, TB>>>(deg, rowptr, bsum, n);
    scan_partials_kernel<<<1, TB>>>(bsum, scan_blocks);
    scan_add_kernel<<<node_blocks, TB>>>(rowptr, cur, bsum, n, e);
    scatter_kernel<<<edge_blocks, TB>>>(ei1, ei1 + e, cur, csr, e);
    // fused softmax + aggregation + bias + relu
    aggr_kernel<<<warp_blocks, TB>>>(rowptr, csr, as_, ad_, h, b1, agg, n, 1);

    // ================= layer 2 =================
    gemm64_kernel<HID><<<gemm_blocks, TB>>>(agg, W2, h, n);
    score_kernel<<<warp_blocks, TB>>>(h, att_src2, att_dst2, as_, ad_, n);
    zero_deg_kernel<<<node_blocks, TB>>>(deg, n);
    hist_kernel<<<edge_blocks, TB>>>(ei2 + e, deg, e);
    scan_block_kernel<<<scan_blocks, TB>>>(deg, rowptr, bsum, n);
    scan_partials_kernel<<<1, TB>>>(bsum, scan_blocks);
    scan_add_kernel<<<node_blocks, TB>>>(rowptr, cur, bsum, n, e);
    scatter_kernel<<<edge_blocks, TB>>>(ei2, ei2 + e, cur, csr, e);
    aggr_kernel<<<warp_blocks, TB>>>(rowptr, csr, as_, ad_, h, b2, agg, n, 0);

    // ================= readout =================
    final_kernel<<<warp_blocks, TB>>>(agg, Wlin, blin, out, n);
}

// round 5
// speedup vs baseline: 1.9544x; 1.6354x over previous
#include <cuda_runtime.h>
#include <cuda_bf16.h>
#include <math_constants.h>

#define NNODES 100000
#define NEDGES 1600000
#define FIN 128
#define HID 64
#define SCAN_CHUNK 1024
#define FULLMASK 0xFFFFFFFFu

// ---------------- scratch (static device globals; no allocation) -------------
__device__ __align__(256) float g_h[NNODES * HID];
__device__ __align__(256) float g_agg[NNODES * HID];
__device__ __align__(256) float g_as[NNODES];
__device__ __align__(256) float g_ad[NNODES];
__device__ __align__(256) int g_deg1[NNODES],        g_deg2[NNODES];
__device__ __align__(256) int g_rp1[NNODES + 1],     g_rp2[NNODES + 1];
__device__ __align__(256) int g_cur1[NNODES],        g_cur2[NNODES];
__device__ __align__(256) int g_csr1[NEDGES],        g_csr2[NEDGES];
__device__ __align__(256) int g_bsum1[256],          g_bsum2[256];

// ---------------- GEMM + fused attention scores (device body) ----------------
// C[n,64] = X[n,K] @ W[K,64]; tile 128 rows x 64 cols, micro 8x4 per thread.
template <int K>
__device__ __forceinline__ void gemm_score_body(int bid,
        const float* __restrict__ X, const float* __restrict__ W,
        const float* __restrict__ att_s, const float* __restrict__ att_d,
        float* __restrict__ C, float* __restrict__ as_, float* __restrict__ ad_,
        int n) {
    __shared__ float Xs[128][36];
    __shared__ float Ws[32][64];
    int tid = threadIdx.x;
    int tx = tid & 15;
    int ty = tid >> 4;
    int row0 = bid * 128;
    float acc[8][4] = {};
    for (int k0 = 0; k0 < K; k0 += 32) {
        for (int l = tid; l < 1024; l += 256) {
            int r = l >> 3, c4 = l & 7;
            int nd = row0 + r;
            float4 v = make_float4(0.f, 0.f, 0.f, 0.f);
            if (nd < n) v = *reinterpret_cast<const float4*>(X + (size_t)nd * K + k0 + c4 * 4);
            *reinterpret_cast<float4*>(&Xs[r][c4 * 4]) = v;
        }
        for (int l = tid; l < 512; l += 256) {
            int kk = l >> 4, c4 = l & 15;
            *reinterpret_cast<float4*>(&Ws[kk][c4 * 4]) =
                *reinterpret_cast<const float4*>(W + (size_t)(k0 + kk) * 64 + c4 * 4);
        }
        __syncthreads();
#pragma unroll
        for (int kk = 0; kk < 32; kk += 4) {
            float4 wv0 = *reinterpret_cast<float4*>(&Ws[kk + 0][tx * 4]);
            float4 wv1 = *reinterpret_cast<float4*>(&Ws[kk + 1][tx * 4]);
            float4 wv2 = *reinterpret_cast<float4*>(&Ws[kk + 2][tx * 4]);
            float4 wv3 = *reinterpret_cast<float4*>(&Ws[kk + 3][tx * 4]);
#pragma unroll
            for (int r = 0; r < 8; r++) {
                float4 xq = *reinterpret_cast<float4*>(&Xs[ty * 8 + r][kk]);
                acc[r][0] += xq.x * wv0.x; acc[r][1] += xq.x * wv0.y;
                acc[r][2] += xq.x * wv0.z; acc[r][3] += xq.x * wv0.w;
                acc[r][0] += xq.y * wv1.x; acc[r][1] += xq.y * wv1.y;
                acc[r][2] += xq.y * wv1.z; acc[r][3] += xq.y * wv1.w;
                acc[r][0] += xq.z * wv2.x; acc[r][1] += xq.z * wv2.y;
                acc[r][2] += xq.z * wv2.z; acc[r][3] += xq.z * wv2.w;
                acc[r][0] += xq.w * wv3.x; acc[r][1] += xq.w * wv3.y;
                acc[r][2] += xq.w * wv3.z; acc[r][3] += xq.w * wv3.w;
            }
        }
        __syncthreads();
    }
    float asv[4], adv[4];
#pragma unroll
    for (int c = 0; c < 4; c++) { asv[c] = att_s[tx * 4 + c]; adv[c] = att_d[tx * 4 + c]; }
#pragma unroll
    for (int r = 0; r < 8; r++) {
        int nd = row0 + ty * 8 + r;
        if (nd < n)
            *reinterpret_cast<float4*>(C + (size_t)nd * 64 + tx * 4) =
                make_float4(acc[r][0], acc[r][1], acc[r][2], acc[r][3]);
        float ps = acc[r][0] * asv[0] + acc[r][1] * asv[1] + acc[r][2] * asv[2] + acc[r][3] * asv[3];
        float pd = acc[r][0] * adv[0] + acc[r][1] * adv[1] + acc[r][2] * adv[2] + acc[r][3] * adv[3];
#pragma unroll
        for (int o = 1; o < 16; o <<= 1) {
            ps += __shfl_xor_sync(FULLMASK, ps, o);
            pd += __shfl_xor_sync(FULLMASK, pd, o);
        }
        if (tx == 0 && nd < n) { as_[nd] = ps; ad_[nd] = pd; }
    }
}

// ---------------- K1: zero both degree arrays --------------------------------
__global__ void zero2_kernel(int* __restrict__ d1, int* __restrict__ d2, int n) {
    int i = blockIdx.x * blockDim.x + threadIdx.x;
    if (i < n) { d1[i] = 0; d2[i] = 0; }
}

// ---------------- K2: gemm_score layer1  ||  hist1  ||  hist2 ----------------
__global__ void gemm1_hist_kernel(const float* __restrict__ X, const float* __restrict__ W,
        const float* __restrict__ att_s, const float* __restrict__ att_d,
        float* __restrict__ C, float* __restrict__ as_, float* __restrict__ ad_, int n,
        int gemm_blocks,
        const int* __restrict__ dst1, int* __restrict__ deg1,
        const int* __restrict__ dst2, int* __restrict__ deg2, int ne, int hb) {
    int bid = blockIdx.x;
    if (bid < gemm_blocks) {
        gemm_score_body<FIN>(bid, X, W, att_s, att_d, C, as_, ad_, n);
        return;
    }
    bid -= gemm_blocks;
    const int* dstp; int* deg;
    if (bid < hb) { dstp = dst1; deg = deg1; }
    else          { bid -= hb; dstp = dst2; deg = deg2; }
    int base = (bid * blockDim.x + threadIdx.x) * 4;
    if (base + 3 < ne) {
        int4 d4 = *reinterpret_cast<const int4*>(dstp + base);
        atomicAdd(&deg[d4.x], 1);
        atomicAdd(&deg[d4.y], 1);
        atomicAdd(&deg[d4.z], 1);
        atomicAdd(&deg[d4.w], 1);
    } else {
        for (int i = base; i < ne; i++) atomicAdd(&deg[dstp[i]], 1);
    }
}

// ---------------- K3: per-chunk scan of both degree arrays -------------------
__global__ void scan_block2_kernel(const int* __restrict__ deg1, const int* __restrict__ deg2,
                                   int* __restrict__ rp1, int* __restrict__ rp2,
                                   int* __restrict__ bs1, int* __restrict__ bs2,
                                   int n, int sb) {
    __shared__ int tsum[256];
    int b = blockIdx.x;
    const int* deg; int* rowptr; int* bsum;
    if (b < sb) { deg = deg1; rowptr = rp1; bsum = bs1; }
    else        { b -= sb; deg = deg2; rowptr = rp2; bsum = bs2; }
    int t = threadIdx.x;
    int base = b * SCAN_CHUNK + t * 4;
    int v[4]; int s = 0;
#pragma unroll
    for (int j = 0; j < 4; j++) { v[j] = (base + j < n) ? deg[base + j] : 0; s += v[j]; }
    tsum[t] = s;
    __syncthreads();
    int acc = s;
    for (int off = 1; off < 256; off <<= 1) {
        int x = (t >= off) ? tsum[t - off] : 0;
        __syncthreads();
        tsum[t] += x;
        __syncthreads();
    }
    int excl = tsum[t] - acc;
    if (t == 255) bsum[b] = tsum[255];     // raw chunk total
    int run = excl;
#pragma unroll
    for (int j = 0; j < 4; j++) {
        if (base + j < n) rowptr[base + j] = run;
        run += v[j];
    }
}

// ---------------- K4: add chunk prefixes (inline partial scan), init cur -----
__global__ void scan_add2_kernel(int* __restrict__ rp1, int* __restrict__ cur1,
                                 const int* __restrict__ bs1,
                                 int* __restrict__ rp2, int* __restrict__ cur2,
                                 const int* __restrict__ bs2,
                                 int n, int e, int node_blocks) {
    __shared__ int red[256];
    int b = blockIdx.x;
    int* rowptr; int* cur; const int* bsum;
    if (b < node_blocks) { rowptr = rp1; cur = cur1; bsum = bs1; }
    else                 { b -= node_blocks; rowptr = rp2; cur = cur2; bsum = bs2; }
    int t = threadIdx.x;
    int c = b >> 2;                        // chunk index (256-node block inside 1024-node chunk)
    red[t] = (t < c) ? bsum[t] : 0;        // c <= 97 < 256
    __syncthreads();
    for (int off = 128; off; off >>= 1) {
        if (t < off) red[t] += red[t + off];
        __syncthreads();
    }
    int prefix = red[0];
    int i = b * 256 + t;
    if (i < n) {
        int v = rowptr[i] + prefix;
        rowptr[i] = v;
        cur[i] = v;
    }
    if (b == 0 && t == 0) rowptr[n] = e;
}

// ---------------- K5: scatter layer 1 ----------------------------------------
__global__ void scatter1_kernel(const int* __restrict__ src, const int* __restrict__ dst,
                                int* __restrict__ cur, int* __restrict__ csr, int ne) {
    int i = blockIdx.x * blockDim.x + threadIdx.x;
    if (i >= ne) return;
    int d = dst[i];
    int p = atomicAdd(&cur[d], 1);
    csr[p] = src[i];
}

// ---------------- aggregation core: flash-style softmax + gather, MLP=8 ------
__device__ __forceinline__ void aggr_core(const int* __restrict__ rowptr,
                                          const int* __restrict__ csr,
                                          const float* __restrict__ as_,
                                          const float* __restrict__ ad_,
                                          const float* __restrict__ h,
                                          int nd, int lane,
                                          float& ro0, float& ro1) {
    int start = rowptr[nd];
    int end = rowptr[nd + 1];
    float adv = ad_[nd];
    float m = -CUDART_INF_F;
    float ssum = 0.f;
    float a0 = 0.f, a1 = 0.f;
    for (int base = start; base < end; base += 32) {
        int i = base + lane;
        bool valid = (i < end);
        int s = valid ? csr[i] : 0;
        float e = -CUDART_INF_F;
        if (valid) {
            float v = as_[s] + adv;
            e = (v > 0.f) ? v : 0.2f * v;
        }
        float cm = e;
#pragma unroll
        for (int o = 16; o; o >>= 1) cm = fmaxf(cm, __shfl_xor_sync(FULLMASK, cm, o));
        float mnew = fmaxf(m, cm);
        float scale = __expf(m - mnew);
        ssum *= scale; a0 *= scale; a1 *= scale;
        float w = valid ? __expf(e - mnew) : 0.f;
        float ws = w;
#pragma unroll
        for (int o = 16; o; o >>= 1) ws += __shfl_xor_sync(FULLMASK, ws, o);
        ssum += ws;
        m = mnew;
        int cnt = min(32, end - base);
        for (int j = 0; j < cnt; j += 8) {          // invalid lanes carry w=0, s=0
            float wv[8]; float2 hv[8];
#pragma unroll
            for (int k = 0; k < 8; k++) {
                int sj = __shfl_sync(FULLMASK, s, j + k);
                wv[k] = __shfl_sync(FULLMASK, w, j + k);
                hv[k] = *reinterpret_cast<const float2*>(h + (size_t)sj * 64 + lane * 2);
            }
#pragma unroll
            for (int k = 0; k < 8; k++) { a0 += wv[k] * hv[k].x; a1 += wv[k] * hv[k].y; }
        }
    }
    float inv = 1.f / (ssum + 1e-16f);
    ro0 = a0 * inv;
    ro1 = a1 * inv;
}

// ---------------- K6: aggr layer1 (+bias+relu)  ||  scatter layer2 -----------
__global__ void aggr_scatter_kernel(const int* __restrict__ rowptr, const int* __restrict__ csr,
        const float* __restrict__ as_, const float* __restrict__ ad_,
        const float* __restrict__ h, const float* __restrict__ bias,
        float* __restrict__ aggout, int n, int warp_blocks,
        const int* __restrict__ src2, const int* __restrict__ dst2,
        int* __restrict__ cur2, int* __restrict__ csr2, int ne) {
    int b = blockIdx.x;
    if (b >= warp_blocks) {                 // scatter for layer 2
        b -= warp_blocks;
        int i = b * blockDim.x + threadIdx.x;
        if (i < ne) {
            int d = dst2[i];
            int p = atomicAdd(&cur2[d], 1);
            csr2[p] = src2[i];
        }
        return;
    }
    int gt = b * blockDim.x + threadIdx.x;
    int nd = gt >> 5;
    int lane = gt & 31;
    if (nd >= n) return;
    float o0, o1;
    aggr_core(rowptr, csr, as_, ad_, h, nd, lane, o0, o1);
    o0 = fmaxf(o0 + bias[lane * 2], 0.f);
    o1 = fmaxf(o1 + bias[lane * 2 + 1], 0.f);
    *reinterpret_cast<float2*>(aggout + (size_t)nd * 64 + lane * 2) = make_float2(o0, o1);
}

// ---------------- K7: gemm_score layer2 --------------------------------------
__global__ void gemm2_kernel(const float* __restrict__ X, const float* __restrict__ W,
        const float* __restrict__ att_s, const float* __restrict__ att_d,
        float* __restrict__ C, float* __restrict__ as_, float* __restrict__ ad_, int n) {
    gemm_score_body<HID>(blockIdx.x, X, W, att_s, att_d, C, as_, ad_, n);
}

// ---------------- K8: aggr layer2 + bias + linear + log_softmax --------------
__global__ void aggr_final_kernel(const int* __restrict__ rowptr, const int* __restrict__ csr,
        const float* __restrict__ as_, const float* __restrict__ ad_,
        const float* __restrict__ h, const float* __restrict__ bias,
        const float* __restrict__ Wlin, const float* __restrict__ blin,
        float* __restrict__ out, int n) {
    __shared__ float Ws[64 * 32];
    for (int i = threadIdx.x; i < 64 * 32; i += blockDim.x) Ws[i] = Wlin[i];
    __syncthreads();
    int gt = blockIdx.x * blockDim.x + threadIdx.x;
    int nd = gt >> 5;
    int lane = gt & 31;
    if (nd >= n) return;
    float o0, o1;
    aggr_core(rowptr, csr, as_, ad_, h, nd, lane, o0, o1);
    o0 += bias[lane * 2];
    o1 += bias[lane * 2 + 1];
    // y[c] = blin[c] + sum_k row[k] * Wlin[k][c], row[2j]=o0@lane j, row[2j+1]=o1@lane j
    float y = blin[lane];
#pragma unroll
    for (int j = 0; j < 32; j++) {
        float r0 = __shfl_sync(FULLMASK, o0, j);
        float r1 = __shfl_sync(FULLMASK, o1, j);
        y += r0 * Ws[(2 * j) * 32 + lane] + r1 * Ws[(2 * j + 1) * 32 + lane];
    }
    float m = y;
#pragma unroll
    for (int o = 16; o; o >>= 1) m = fmaxf(m, __shfl_xor_sync(FULLMASK, m, o));
    float ex = __expf(y - m);
    float ss = ex;
#pragma unroll
    for (int o = 16; o; o >>= 1) ss += __shfl_xor_sync(FULLMASK, ss, o);
    out[(size_t)nd * 32 + lane] = y - m - __logf(ss);
}

// ---------------- launch ------------------------------------------------------
extern "C" void kernel_launch(void* const* d_in, const int* in_sizes, int n_in,
                              void* d_out, int out_size) {
    const float* x        = (const float*)d_in[0];
    const int*   ei1      = (const int*)d_in[1];
    const int*   ei2      = (const int*)d_in[2];
    const float* W1       = (const float*)d_in[3];
    const float* att_src1 = (const float*)d_in[4];
    const float* att_dst1 = (const float*)d_in[5];
    const float* b1       = (const float*)d_in[6];
    const float* W2       = (const float*)d_in[7];
    const float* att_src2 = (const float*)d_in[8];
    const float* att_dst2 = (const float*)d_in[9];
    const float* b2       = (const float*)d_in[10];
    const float* Wlin     = (const float*)d_in[11];
    const float* blin     = (const float*)d_in[12];
    float* out = (float*)d_out;

    const int n = in_sizes[0] / FIN;       // 100000
    const int e = in_sizes[1] / 2;         // 1600000

    float *h, *agg, *as_, *ad_;
    int *deg1, *rp1, *cur1, *csr1, *bs1;
    int *deg2, *rp2, *cur2, *csr2, *bs2;
    cudaGetSymbolAddress((void**)&h,    g_h);
    cudaGetSymbolAddress((void**)&agg,  g_agg);
    cudaGetSymbolAddress((void**)&as_,  g_as);
    cudaGetSymbolAddress((void**)&ad_,  g_ad);
    cudaGetSymbolAddress((void**)&deg1, g_deg1);
    cudaGetSymbolAddress((void**)&rp1,  g_rp1);
    cudaGetSymbolAddress((void**)&cur1, g_cur1);
    cudaGetSymbolAddress((void**)&csr1, g_csr1);
    cudaGetSymbolAddress((void**)&bs1,  g_bsum1);
    cudaGetSymbolAddress((void**)&deg2, g_deg2);
    cudaGetSymbolAddress((void**)&rp2,  g_rp2);
    cudaGetSymbolAddress((void**)&cur2, g_cur2);
    cudaGetSymbolAddress((void**)&csr2, g_csr2);
    cudaGetSymbolAddress((void**)&bs2,  g_bsum2);

    const int TB = 256;
    int gemm_blocks = (n + 127) / 128;                 // 782
    int node_blocks = (n + TB - 1) / TB;               // 391
    int warp_blocks = (n * 32 + TB - 1) / TB;          // 12500
    int eb          = (e + TB - 1) / TB;               // 6250
    int hb          = (e + 4 * TB - 1) / (4 * TB);     // 1563
    int sb          = (n + SCAN_CHUNK - 1) / SCAN_CHUNK; // 98

    // K1: zero degree arrays
    zero2_kernel<<<node_blocks, TB>>>(deg1, deg2, n);
    // K2: gemm1+score  ||  hist1  ||  hist2
    gemm1_hist_kernel<<<gemm_blocks + 2 * hb, TB>>>(
        x, W1, att_src1, att_dst1, h, as_, ad_, n, gemm_blocks,
        ei1 + e, deg1, ei2 + e, deg2, e, hb);
    // K3/K4: rowptr scans (both layers)
    scan_block2_kernel<<<2 * sb, TB>>>(deg1, deg2, rp1, rp2, bs1, bs2, n, sb);
    scan_add2_kernel<<<2 * node_blocks, TB>>>(rp1, cur1, bs1, rp2, cur2, bs2, n, e, node_blocks);
    // K5: scatter layer 1
    scatter1_kernel<<<eb, TB>>>(ei1, ei1 + e, cur1, csr1, e);
    // K6: aggr layer1 (+bias+relu)  ||  scatter layer 2
    aggr_scatter_kernel<<<warp_blocks + eb, TB>>>(
        rp1, csr1, as_, ad_, h, b1, agg, n, warp_blocks,
        ei2, ei2 + e, cur2, csr2, e);
    // K7: gemm2+score
    gemm2_kernel<<<gemm_blocks, TB>>>(agg, W2, att_src2, att_dst2, h, as_, ad_, n);
    // K8: aggr layer2 + linear + log_softmax
    aggr_final_kernel<<<warp_blocks, TB>>>(
        rp2, csr2, as_, ad_, h, b2, Wlin, blin, out, n);
}